// round 11
// baseline (speedup 1.0000x reference)
#include <cuda_runtime.h>

#define B_     16
#define N_     50000
#define INC_   128
#define HID_   64
#define NC_    512
#define TOTAL_ (B_ * N_)     // 800000
#define BINS_  (B_ * NC_)    // 8192
#define CAP_   256           // fixed per-bin capacity (mean 97.7, sigma 9.9)
#define NTILES (TOTAL_ / 128)
#define P2_    68            // uint2 pitch: 2*68 ≡ 8 (mod 32) -> LDS64 banks
                             // {8*tig+2g, +1}: perfect 32-bank cover/half-warp

// ---- scratch (no allocations allowed; __device__ globals, zero-init) ----
__device__ int   g_cursor[BINS_];
__device__ int   g_binidx[BINS_ * CAP_];     // bin bc at [bc<<8 ..]
__device__ float g_segmax[BINS_ * HID_];     // 2 MB, L2-resident

// ---------------------------------------------------------------------------
// bf16 split helper: f = hi + lo (each bf16), packed as bf16x2 (lo half = f0).
// ---------------------------------------------------------------------------
__device__ __forceinline__ void split2(float f0, float f1,
                                       unsigned& hi, unsigned& lo) {
    unsigned h;
    asm("cvt.rn.bf16x2.f32 %0, %1, %2;" : "=r"(h) : "f"(f1), "f"(f0));
    float h0 = __uint_as_float(h << 16);
    float h1 = __uint_as_float(h & 0xffff0000u);
    float r0 = f0 - h0, r1 = f1 - h1;
    unsigned l;
    asm("cvt.rn.bf16x2.f32 %0, %1, %2;" : "=r"(l) : "f"(r1), "f"(r0));
    hi = h; lo = l;
}

#define MMA_BF16(c, a, b0v, b1v)                                              \
    asm volatile(                                                             \
        "mma.sync.aligned.m16n8k16.row.col.f32.bf16.bf16.f32 "                \
        "{%0,%1,%2,%3}, {%4,%5,%6,%7}, {%8,%9}, {%0,%1,%2,%3};"               \
        : "+f"((c)[0]), "+f"((c)[1]), "+f"((c)[2]), "+f"((c)[3])              \
        : "r"((a)[0]), "r"((a)[1]), "r"((a)[2]), "r"((a)[3]),                 \
          "r"(b0v), "r"(b1v))

// ---------------------------------------------------------------------------
// PERSISTENT encode on tensor cores: h = relu(LN(x @ W + b)), bf16x3 split.
// 592 blocks (4/SM) of 128 threads; W staged once as packed (hi,lo) uint2.
// Each warp now covers 32 nodes (2 m-tiles) x 64 cols so the SAME B-fragment
// LDS feeds 2x the MMA work (B smem bytes/node halved vs R9), and each
// B fetch is one LDS64 instead of 2 LDS32 (issue count halved).
// Fused cursor-scatter per tile. LN is quad-local via two shfl.xor.
// ---------------------------------------------------------------------------
#define PGRID 592

__global__ __launch_bounds__(128, 4) void encode_kernel(
    const float* __restrict__ x, const int* __restrict__ cluster,
    const float* __restrict__ W,
    const float* __restrict__ bias, const float* __restrict__ gamma,
    const float* __restrict__ beta, float* __restrict__ out)
{
    __shared__ uint2 sW[64 * P2_];           // [k2][n] = (hi, lo), pitch 68
    __shared__ float sB[HID_], sG[HID_], sBt[HID_];

    int tid = threadIdx.x;

    // ---- stage W once (packed bf16x2 hi/lo pairs) ----
#pragma unroll
    for (int it = 0; it < 32; it++) {
        int idx = tid + it * 128;              // 4096 packed entries
        int k2 = idx >> 6, n = idx & 63;
        float f0 = W[(2 * k2) * 64 + n];       // coalesced (n contiguous)
        float f1 = W[(2 * k2 + 1) * 64 + n];
        unsigned h, l;
        split2(f0, f1, h, l);
        sW[k2 * P2_ + n] = make_uint2(h, l);
    }
    if (tid < HID_) { sB[tid] = bias[tid]; sG[tid] = gamma[tid]; sBt[tid] = beta[tid]; }
    __syncthreads();

    int warp = tid >> 5, lane = tid & 31;
    int g = lane >> 2, tig = lane & 3;

    for (int tile = blockIdx.x; tile < NTILES; tile += PGRID) {
        int blockbase = tile * 128;

        // ---- fused scatter (all 128 threads; latency hidden under GEMM) ----
        {
            int node = blockbase + tid;
            int b = node / N_;
            int n = node - b * N_;
            int bc = (b << 9) + cluster[node];
            int pos = atomicAdd(&g_cursor[bc], 1);
            g_binidx[(bc << 8) + pos] = n;
        }

        int wb = blockbase + warp * 32;        // warp's first node (32 nodes)

        float acc0[8][4], acc1[8][4];
#pragma unroll
        for (int t = 0; t < 8; t++)
#pragma unroll
            for (int c = 0; c < 4; c++) { acc0[t][c] = 0.f; acc1[t][c] = 0.f; }

        const float2* xr0 = (const float2*)(x + (size_t)(wb + g) * INC_);
        const float2* xr1 = (const float2*)(x + (size_t)(wb + g + 8) * INC_);
        const float2* xr2 = (const float2*)(x + (size_t)(wb + g + 16) * INC_);
        const float2* xr3 = (const float2*)(x + (size_t)(wb + g + 24) * INC_);

#pragma unroll
        for (int kt = 0; kt < 8; kt++) {       // k-tiles of 16
            int k2base = kt * 8;
            float2 a00 = xr0[k2base + tig], a01 = xr0[k2base + tig + 4];
            float2 a10 = xr1[k2base + tig], a11 = xr1[k2base + tig + 4];
            float2 a20 = xr2[k2base + tig], a21 = xr2[k2base + tig + 4];
            float2 a30 = xr3[k2base + tig], a31 = xr3[k2base + tig + 4];

            unsigned ahi0[4], alo0[4], ahi1[4], alo1[4];
            split2(a00.x, a00.y, ahi0[0], alo0[0]);   // m-tile 0: rows g, g+8
            split2(a10.x, a10.y, ahi0[1], alo0[1]);
            split2(a01.x, a01.y, ahi0[2], alo0[2]);
            split2(a11.x, a11.y, ahi0[3], alo0[3]);
            split2(a20.x, a20.y, ahi1[0], alo1[0]);   // m-tile 1: rows g+16, g+24
            split2(a30.x, a30.y, ahi1[1], alo1[1]);
            split2(a21.x, a21.y, ahi1[2], alo1[2]);
            split2(a31.x, a31.y, ahi1[3], alo1[3]);

            int ra = (k2base + tig) * P2_;
            int rb = (k2base + tig + 4) * P2_;
#pragma unroll
            for (int t = 0; t < 8; t++) {
                int ncol = t * 8 + g;
                uint2 w0 = sW[ra + ncol];      // (bh0, bl0) one LDS64
                uint2 w1 = sW[rb + ncol];      // (bh1, bl1)
                MMA_BF16(acc0[t], ahi0, w0.x, w1.x);   // hi * Hi
                MMA_BF16(acc1[t], ahi1, w0.x, w1.x);
                MMA_BF16(acc0[t], ahi0, w0.y, w1.y);   // hi * Lo
                MMA_BF16(acc1[t], ahi1, w0.y, w1.y);
                MMA_BF16(acc0[t], alo0, w0.x, w1.x);   // lo * Hi
                MMA_BF16(acc1[t], alo1, w0.x, w1.x);
            }
        }

        // ---- epilogue: bias, LN stats (quad-local), relu, store ----
        float s0 = 0.f, q0 = 0.f, s1 = 0.f, q1 = 0.f;
        float s2 = 0.f, q2 = 0.f, s3 = 0.f, q3 = 0.f;
#pragma unroll
        for (int t = 0; t < 8; t++) {
            int n0 = t * 8 + 2 * tig;
            float b0v = sB[n0], b1v = sB[n0 + 1];
            acc0[t][0] += b0v; acc0[t][1] += b1v;    // row g
            acc0[t][2] += b0v; acc0[t][3] += b1v;    // row g+8
            acc1[t][0] += b0v; acc1[t][1] += b1v;    // row g+16
            acc1[t][2] += b0v; acc1[t][3] += b1v;    // row g+24
            s0 += acc0[t][0] + acc0[t][1];
            q0 = fmaf(acc0[t][0], acc0[t][0], q0);
            q0 = fmaf(acc0[t][1], acc0[t][1], q0);
            s1 += acc0[t][2] + acc0[t][3];
            q1 = fmaf(acc0[t][2], acc0[t][2], q1);
            q1 = fmaf(acc0[t][3], acc0[t][3], q1);
            s2 += acc1[t][0] + acc1[t][1];
            q2 = fmaf(acc1[t][0], acc1[t][0], q2);
            q2 = fmaf(acc1[t][1], acc1[t][1], q2);
            s3 += acc1[t][2] + acc1[t][3];
            q3 = fmaf(acc1[t][2], acc1[t][2], q3);
            q3 = fmaf(acc1[t][3], acc1[t][3], q3);
        }
#pragma unroll
        for (int w = 1; w <= 2; w <<= 1) {
            s0 += __shfl_xor_sync(0xffffffffu, s0, w);
            q0 += __shfl_xor_sync(0xffffffffu, q0, w);
            s1 += __shfl_xor_sync(0xffffffffu, s1, w);
            q1 += __shfl_xor_sync(0xffffffffu, q1, w);
            s2 += __shfl_xor_sync(0xffffffffu, s2, w);
            q2 += __shfl_xor_sync(0xffffffffu, q2, w);
            s3 += __shfl_xor_sync(0xffffffffu, s3, w);
            q3 += __shfl_xor_sync(0xffffffffu, q3, w);
        }
        float mu0 = s0 * (1.f / 64.f);
        float rs0 = rsqrtf(q0 * (1.f / 64.f) - mu0 * mu0 + 1e-5f);
        float mu1 = s1 * (1.f / 64.f);
        float rs1 = rsqrtf(q1 * (1.f / 64.f) - mu1 * mu1 + 1e-5f);
        float mu2 = s2 * (1.f / 64.f);
        float rs2 = rsqrtf(q2 * (1.f / 64.f) - mu2 * mu2 + 1e-5f);
        float mu3 = s3 * (1.f / 64.f);
        float rs3 = rsqrtf(q3 * (1.f / 64.f) - mu3 * mu3 + 1e-5f);

        float* o0 = out + (size_t)(wb + g) * 128;
        float* o1 = out + (size_t)(wb + g + 8) * 128;
        float* o2 = out + (size_t)(wb + g + 16) * 128;
        float* o3 = out + (size_t)(wb + g + 24) * 128;
#pragma unroll
        for (int t = 0; t < 8; t++) {
            int n0 = t * 8 + 2 * tig;
            float g0 = sG[n0], g1 = sG[n0 + 1], e0 = sBt[n0], e1 = sBt[n0 + 1];
            float2 v;
            v.x = fmaxf(fmaf((acc0[t][0] - mu0) * rs0, g0, e0), 0.f);
            v.y = fmaxf(fmaf((acc0[t][1] - mu0) * rs0, g1, e1), 0.f);
            *(float2*)(o0 + n0) = v;
            v.x = fmaxf(fmaf((acc0[t][2] - mu1) * rs1, g0, e0), 0.f);
            v.y = fmaxf(fmaf((acc0[t][3] - mu1) * rs1, g1, e1), 0.f);
            *(float2*)(o1 + n0) = v;
            v.x = fmaxf(fmaf((acc1[t][0] - mu2) * rs2, g0, e0), 0.f);
            v.y = fmaxf(fmaf((acc1[t][1] - mu2) * rs2, g1, e1), 0.f);
            *(float2*)(o2 + n0) = v;
            v.x = fmaxf(fmaf((acc1[t][2] - mu3) * rs3, g0, e0), 0.f);
            v.y = fmaxf(fmaf((acc1[t][3] - mu3) * rs3, g1, e1), 0.f);
            *(float2*)(o3 + n0) = v;
        }
    }
}

// ---------------------------------------------------------------------------
// Phase A: segmax only. One block per (batch,cluster): gather member h-rows,
// max-reduce, write the 64-float max row into g_segmax (2MB, L2-resident).
// Thread 0 alone reads AND resets the cursor (race-free), sync publishes it.
// ---------------------------------------------------------------------------
__global__ __launch_bounds__(256) void segmax_kernel(const float* __restrict__ out) {
    int bc = blockIdx.x;
    int b  = bc >> 9;
    int e  = threadIdx.x >> 4;
    int d4 = threadIdx.x & 15;

    __shared__ int    scnt;
    __shared__ int    sidx[CAP_];
    __shared__ float4 sm[256];

    if (threadIdx.x == 0) {
        scnt = g_cursor[bc];      // read-then-reset by ONE thread: race-free
        g_cursor[bc] = 0;         // ready for next graph replay
    }
    __syncthreads();
    int cnt = scnt;

    if (threadIdx.x < cnt) sidx[threadIdx.x] = g_binidx[(bc << 8) + threadIdx.x];
    __syncthreads();

    size_t rowbase = (size_t)b * N_ * 128;

    float4 m = make_float4(-3.402823466e38f, -3.402823466e38f,
                           -3.402823466e38f, -3.402823466e38f);
    for (int i = e; i < cnt; i += 16) {
        int n = sidx[i];
        float4 v = ((const float4*)(out + rowbase + (size_t)n * 128))[d4];
        m.x = fmaxf(m.x, v.x); m.y = fmaxf(m.y, v.y);
        m.z = fmaxf(m.z, v.z); m.w = fmaxf(m.w, v.w);
    }
    sm[threadIdx.x] = m;
    __syncthreads();
#pragma unroll
    for (int off = 128; off >= 16; off >>= 1) {
        if (threadIdx.x < off) {
            float4 a = sm[threadIdx.x], c = sm[threadIdx.x + off];
            a.x = fmaxf(a.x, c.x); a.y = fmaxf(a.y, c.y);
            a.z = fmaxf(a.z, c.z); a.w = fmaxf(a.w, c.w);
            sm[threadIdx.x] = a;
        }
        __syncthreads();
    }
    if (threadIdx.x < 16)
        ((float4*)(g_segmax + bc * HID_))[d4] = sm[d4];
}

// ---------------------------------------------------------------------------
// Phase B: broadcast. Pure streaming: each node reads its cluster's segmax
// row (L2-hot 2MB) and writes out[node][64:128] coalesced. 16 nodes/block.
// ---------------------------------------------------------------------------
__global__ __launch_bounds__(256) void bcast_kernel(
    const int* __restrict__ cluster, float* __restrict__ out)
{
    int node   = blockIdx.x * 16 + (threadIdx.x >> 4);
    int lane16 = threadIdx.x & 15;
    int b = node / N_;
    int c = cluster[node];
    float4 v = ((const float4*)(g_segmax + ((size_t)(b << 9) + c) * HID_))[lane16];
    ((float4*)(out + (size_t)node * 128 + 64))[lane16] = v;
}

// ---------------------------------------------------------------------------
extern "C" void kernel_launch(void* const* d_in, const int* in_sizes, int n_in,
                              void* d_out, int out_size) {
    const float* x       = (const float*)d_in[0];
    const int*   cluster = (const int*)  d_in[1];
    const float* W       = (const float*)d_in[2];
    const float* bias    = (const float*)d_in[3];
    const float* gamma   = (const float*)d_in[4];
    const float* beta    = (const float*)d_in[5];
    float* out = (float*)d_out;

    encode_kernel<<<PGRID, 128>>>(x, cluster, W, bias, gamma, beta, out);
    segmax_kernel<<<BINS_, 256>>>(out);
    bcast_kernel<<<TOTAL_ / 16, 256>>>(cluster, out);
}

// round 14
// speedup vs baseline: 1.0459x; 1.0459x over previous
#include <cuda_runtime.h>

#define B_     16
#define N_     50000
#define INC_   128
#define HID_   64
#define NC_    512
#define TOTAL_ (B_ * N_)     // 800000
#define BINS_  (B_ * NC_)    // 8192
#define CAP_   256           // fixed per-bin capacity (mean 97.7, sigma 9.9)
#define NTILES (TOTAL_ / 128)
#define P2_    68            // uint2 pitch: per half-warp, banks 8*tig+2g
                             // cover all 32 exactly once -> LDS64 conflict-free

// ---- scratch (no allocations allowed; __device__ globals, zero-init) ----
__device__ int g_cursor[BINS_];
__device__ int g_binidx[BINS_ * CAP_];       // bin bc at [bc<<8 ..]

// ---------------------------------------------------------------------------
// bf16 split helper: f = hi + lo (each bf16), packed as bf16x2 (lo half = f0).
// ---------------------------------------------------------------------------
__device__ __forceinline__ void split2(float f0, float f1,
                                       unsigned& hi, unsigned& lo) {
    unsigned h;
    asm("cvt.rn.bf16x2.f32 %0, %1, %2;" : "=r"(h) : "f"(f1), "f"(f0));
    float h0 = __uint_as_float(h << 16);
    float h1 = __uint_as_float(h & 0xffff0000u);
    float r0 = f0 - h0, r1 = f1 - h1;
    unsigned l;
    asm("cvt.rn.bf16x2.f32 %0, %1, %2;" : "=r"(l) : "f"(r1), "f"(r0));
    hi = h; lo = l;
}

#define MMA_BF16(c, a, b0v, b1v)                                              \
    asm volatile(                                                             \
        "mma.sync.aligned.m16n8k16.row.col.f32.bf16.bf16.f32 "                \
        "{%0,%1,%2,%3}, {%4,%5,%6,%7}, {%8,%9}, {%0,%1,%2,%3};"               \
        : "+f"((c)[0]), "+f"((c)[1]), "+f"((c)[2]), "+f"((c)[3])              \
        : "r"((a)[0]), "r"((a)[1]), "r"((a)[2]), "r"((a)[3]),                 \
          "r"(b0v), "r"(b1v))

// ---------------------------------------------------------------------------
// PERSISTENT encode on tensor cores (R9 config + LDS64 B fetch):
// h = relu(LN(x @ W + b)), bf16x3 split. 296 blocks (2/SM) of 256 threads;
// W staged once as packed (hi,lo) uint2, pitch 68. Warp covers 16 nodes x 64
// cols (1 m-tile: keeps regs ~115, no spill — the R11 2-m-tile variant hit
// the 128-reg RF cap and spilled). B fetch = 1 LDS64 instead of 2 LDS32.
// Fused cursor-scatter per tile. LN is quad-local via two shfl.xor.
// ---------------------------------------------------------------------------
#define PGRID 296

__global__ __launch_bounds__(256, 2) void encode_kernel(
    const float* __restrict__ x, const int* __restrict__ cluster,
    const float* __restrict__ W,
    const float* __restrict__ bias, const float* __restrict__ gamma,
    const float* __restrict__ beta, float* __restrict__ out)
{
    __shared__ uint2 sW[64 * P2_];           // [k2][n] = (hi, lo)
    __shared__ float sB[HID_], sG[HID_], sBt[HID_];

    int tid = threadIdx.x;

    // ---- stage W once (packed bf16x2 hi/lo pairs) ----
#pragma unroll
    for (int it = 0; it < 16; it++) {
        int idx = tid + it * 256;              // 4096 packed entries
        int k2 = idx >> 6, n = idx & 63;
        float f0 = W[(2 * k2) * 64 + n];       // coalesced (n contiguous)
        float f1 = W[(2 * k2 + 1) * 64 + n];
        unsigned h, l;
        split2(f0, f1, h, l);
        sW[k2 * P2_ + n] = make_uint2(h, l);
    }
    if (tid < HID_) { sB[tid] = bias[tid]; sG[tid] = gamma[tid]; sBt[tid] = beta[tid]; }
    __syncthreads();

    int warp = tid >> 5, lane = tid & 31;
    int g = lane >> 2, tig = lane & 3;

    for (int tile = blockIdx.x; tile < NTILES; tile += PGRID) {
        int blockbase = tile * 128;

        // ---- fused scatter (threads 0..127; latency hidden under GEMM) ----
        if (tid < 128) {
            int node = blockbase + tid;
            int b = node / N_;
            int n = node - b * N_;
            int bc = (b << 9) + cluster[node];
            int pos = atomicAdd(&g_cursor[bc], 1);
            g_binidx[(bc << 8) + pos] = n;
        }

        int wb = blockbase + warp * 16;        // warp's first node

        float acc[8][4];
#pragma unroll
        for (int t = 0; t < 8; t++)
#pragma unroll
            for (int c = 0; c < 4; c++) acc[t][c] = 0.f;

        const float2* xr0 = (const float2*)(x + (size_t)(wb + g) * INC_);
        const float2* xr1 = (const float2*)(x + (size_t)(wb + g + 8) * INC_);

#pragma unroll
        for (int kt = 0; kt < 8; kt++) {       // k-tiles of 16
            int k2base = kt * 8;
            float2 f00 = xr0[k2base + tig];
            float2 f10 = xr1[k2base + tig];
            float2 f01 = xr0[k2base + tig + 4];
            float2 f11 = xr1[k2base + tig + 4];

            unsigned ahi[4], alo[4];
            split2(f00.x, f00.y, ahi[0], alo[0]);
            split2(f10.x, f10.y, ahi[1], alo[1]);
            split2(f01.x, f01.y, ahi[2], alo[2]);
            split2(f11.x, f11.y, ahi[3], alo[3]);

            int ra = (k2base + tig) * P2_;
            int rb = (k2base + tig + 4) * P2_;
#pragma unroll
            for (int t = 0; t < 8; t++) {
                int ncol = t * 8 + g;
                uint2 w0 = sW[ra + ncol];      // (bh, bl) in one LDS64
                uint2 w1 = sW[rb + ncol];
                MMA_BF16(acc[t], ahi, w0.x, w1.x);   // hi * Hi
                MMA_BF16(acc[t], ahi, w0.y, w1.y);   // hi * Lo
                MMA_BF16(acc[t], alo, w0.x, w1.x);   // lo * Hi
            }
        }

        // ---- epilogue: bias, LN stats (quad-local), relu, store ----
        float s0 = 0.f, q0 = 0.f, s1 = 0.f, q1 = 0.f;
#pragma unroll
        for (int t = 0; t < 8; t++) {
            int n0 = t * 8 + 2 * tig;
            float b0v = sB[n0], b1v = sB[n0 + 1];
            acc[t][0] += b0v; acc[t][1] += b1v;    // row g
            acc[t][2] += b0v; acc[t][3] += b1v;    // row g+8
            s0 += acc[t][0] + acc[t][1];
            q0 = fmaf(acc[t][0], acc[t][0], q0);
            q0 = fmaf(acc[t][1], acc[t][1], q0);
            s1 += acc[t][2] + acc[t][3];
            q1 = fmaf(acc[t][2], acc[t][2], q1);
            q1 = fmaf(acc[t][3], acc[t][3], q1);
        }
#pragma unroll
        for (int w = 1; w <= 2; w <<= 1) {
            s0 += __shfl_xor_sync(0xffffffffu, s0, w);
            q0 += __shfl_xor_sync(0xffffffffu, q0, w);
            s1 += __shfl_xor_sync(0xffffffffu, s1, w);
            q1 += __shfl_xor_sync(0xffffffffu, q1, w);
        }
        float mu0 = s0 * (1.f / 64.f);
        float rs0 = rsqrtf(q0 * (1.f / 64.f) - mu0 * mu0 + 1e-5f);
        float mu1 = s1 * (1.f / 64.f);
        float rs1 = rsqrtf(q1 * (1.f / 64.f) - mu1 * mu1 + 1e-5f);

        float* o0 = out + (size_t)(wb + g) * 128;
        float* o1 = out + (size_t)(wb + g + 8) * 128;
#pragma unroll
        for (int t = 0; t < 8; t++) {
            int n0 = t * 8 + 2 * tig;
            float g0 = sG[n0], g1 = sG[n0 + 1], e0 = sBt[n0], e1 = sBt[n0 + 1];
            float2 v0, v1;
            v0.x = fmaxf(fmaf((acc[t][0] - mu0) * rs0, g0, e0), 0.f);
            v0.y = fmaxf(fmaf((acc[t][1] - mu0) * rs0, g1, e1), 0.f);
            v1.x = fmaxf(fmaf((acc[t][2] - mu1) * rs1, g0, e0), 0.f);
            v1.y = fmaxf(fmaf((acc[t][3] - mu1) * rs1, g1, e1), 0.f);
            *(float2*)(o0 + n0) = v0;
            *(float2*)(o1 + n0) = v1;
        }
    }
}

// ---------------------------------------------------------------------------
// FUSED segmax + broadcast: one block per (batch,cluster).
// 32 entry-lanes x 8 dim-threads (256 thr); each thread carries 2 float4s of
// the 64-float row -> 32 member rows in flight (2x the old MLP). Reduce the
// 32 partials in smem, then the same lanes broadcast the max row into every
// member's out[node][64:128]. No segmax buffer, no cluster re-read, 1 launch.
// Thread 0 alone reads AND resets the cursor (race-free), sync publishes it.
// ---------------------------------------------------------------------------
__global__ __launch_bounds__(256) void seg_kernel(float* __restrict__ out) {
    int bc = blockIdx.x;
    int b  = bc >> 9;
    int e  = threadIdx.x >> 3;     // 32 entry lanes
    int d8 = threadIdx.x & 7;      // covers float4 slots d8 and d8+8

    __shared__ int    scnt;
    __shared__ int    sidx[CAP_];
    __shared__ float4 sm0[256], sm1[256];

    if (threadIdx.x == 0) {
        scnt = g_cursor[bc];       // read-then-reset by ONE thread: race-free
        g_cursor[bc] = 0;          // ready for next graph replay
    }
    __syncthreads();
    int cnt = scnt;

    if (threadIdx.x < cnt) sidx[threadIdx.x] = g_binidx[(bc << 8) + threadIdx.x];
    __syncthreads();

    size_t rowbase = (size_t)b * N_ * 128;

    float4 m0 = make_float4(-3.402823466e38f, -3.402823466e38f,
                            -3.402823466e38f, -3.402823466e38f);
    float4 m1 = m0;
    for (int i = e; i < cnt; i += 32) {
        const float4* r = (const float4*)(out + rowbase + (size_t)sidx[i] * 128);
        float4 v0 = r[d8], v1 = r[d8 + 8];
        m0.x = fmaxf(m0.x, v0.x); m0.y = fmaxf(m0.y, v0.y);
        m0.z = fmaxf(m0.z, v0.z); m0.w = fmaxf(m0.w, v0.w);
        m1.x = fmaxf(m1.x, v1.x); m1.y = fmaxf(m1.y, v1.y);
        m1.z = fmaxf(m1.z, v1.z); m1.w = fmaxf(m1.w, v1.w);
    }
    sm0[threadIdx.x] = m0;
    sm1[threadIdx.x] = m1;
    __syncthreads();
    // tree-reduce the 32 entry lanes; offsets multiples of 8 keep d8 aligned
#pragma unroll
    for (int off = 128; off >= 8; off >>= 1) {
        if (threadIdx.x < off) {
            float4 a0 = sm0[threadIdx.x], c0 = sm0[threadIdx.x + off];
            float4 a1 = sm1[threadIdx.x], c1 = sm1[threadIdx.x + off];
            a0.x = fmaxf(a0.x, c0.x); a0.y = fmaxf(a0.y, c0.y);
            a0.z = fmaxf(a0.z, c0.z); a0.w = fmaxf(a0.w, c0.w);
            a1.x = fmaxf(a1.x, c1.x); a1.y = fmaxf(a1.y, c1.y);
            a1.z = fmaxf(a1.z, c1.z); a1.w = fmaxf(a1.w, c1.w);
            sm0[threadIdx.x] = a0;
            sm1[threadIdx.x] = a1;
        }
        __syncthreads();
    }
    float4 v0 = sm0[d8], v1 = sm1[d8];
    for (int i = e; i < cnt; i += 32) {
        float4* w = (float4*)(out + rowbase + (size_t)sidx[i] * 128 + 64);
        w[d8]     = v0;
        w[d8 + 8] = v1;
    }
}

// ---------------------------------------------------------------------------
extern "C" void kernel_launch(void* const* d_in, const int* in_sizes, int n_in,
                              void* d_out, int out_size) {
    const float* x       = (const float*)d_in[0];
    const int*   cluster = (const int*)  d_in[1];
    const float* W       = (const float*)d_in[2];
    const float* bias    = (const float*)d_in[3];
    const float* gamma   = (const float*)d_in[4];
    const float* beta    = (const float*)d_in[5];
    float* out = (float*)d_out;

    encode_kernel<<<PGRID, 256>>>(x, cluster, W, bias, gamma, beta, out);
    seg_kernel<<<BINS_, 256>>>(out);
}

// round 16
// speedup vs baseline: 1.2455x; 1.1909x over previous
#include <cuda_runtime.h>

#define B_     16
#define N_     50000
#define INC_   128
#define HID_   64
#define NC_    512
#define TOTAL_ (B_ * N_)     // 800000
#define BINS_  (B_ * NC_)    // 8192
#define CAP_   256           // fixed per-bin capacity (mean 97.7, sigma 9.9)
#define NTILES (TOTAL_ / 128)
#define P2_    68            // uint2 pitch: per half-warp, banks 8*tig+2g
                             // cover all 32 exactly once -> LDS64 conflict-free

// ---- scratch (no allocations allowed; __device__ globals, zero-init) ----
__device__ int g_cursor[BINS_];
__device__ int g_binidx[BINS_ * CAP_];       // bin bc at [bc<<8 ..]

// ---------------------------------------------------------------------------
// bf16 split helper: f = hi + lo (each bf16), packed as bf16x2 (lo half = f0).
// ---------------------------------------------------------------------------
__device__ __forceinline__ void split2(float f0, float f1,
                                       unsigned& hi, unsigned& lo) {
    unsigned h;
    asm("cvt.rn.bf16x2.f32 %0, %1, %2;" : "=r"(h) : "f"(f1), "f"(f0));
    float h0 = __uint_as_float(h << 16);
    float h1 = __uint_as_float(h & 0xffff0000u);
    float r0 = f0 - h0, r1 = f1 - h1;
    unsigned l;
    asm("cvt.rn.bf16x2.f32 %0, %1, %2;" : "=r"(l) : "f"(r1), "f"(r0));
    hi = h; lo = l;
}

#define MMA_BF16(c, a, b0v, b1v)                                              \
    asm volatile(                                                             \
        "mma.sync.aligned.m16n8k16.row.col.f32.bf16.bf16.f32 "                \
        "{%0,%1,%2,%3}, {%4,%5,%6,%7}, {%8,%9}, {%0,%1,%2,%3};"               \
        : "+f"((c)[0]), "+f"((c)[1]), "+f"((c)[2]), "+f"((c)[3])              \
        : "r"((a)[0]), "r"((a)[1]), "r"((a)[2]), "r"((a)[3]),                 \
          "r"(b0v), "r"(b1v))

// ---------------------------------------------------------------------------
// PERSISTENT encode on tensor cores (unchanged from R14, 300.1us best):
// h = relu(LN(x @ W + b)), bf16x3 split. 296 blocks (2/SM) of 256 threads;
// W staged once as packed (hi,lo) uint2, pitch 68; B fetch = 1 LDS64.
// Fused cursor-scatter per tile. LN is quad-local via two shfl.xor.
// ---------------------------------------------------------------------------
#define PGRID 296

__global__ __launch_bounds__(256, 2) void encode_kernel(
    const float* __restrict__ x, const int* __restrict__ cluster,
    const float* __restrict__ W,
    const float* __restrict__ bias, const float* __restrict__ gamma,
    const float* __restrict__ beta, float* __restrict__ out)
{
    __shared__ uint2 sW[64 * P2_];           // [k2][n] = (hi, lo)
    __shared__ float sB[HID_], sG[HID_], sBt[HID_];

    int tid = threadIdx.x;

    // ---- stage W once (packed bf16x2 hi/lo pairs) ----
#pragma unroll
    for (int it = 0; it < 16; it++) {
        int idx = tid + it * 256;              // 4096 packed entries
        int k2 = idx >> 6, n = idx & 63;
        float f0 = W[(2 * k2) * 64 + n];       // coalesced (n contiguous)
        float f1 = W[(2 * k2 + 1) * 64 + n];
        unsigned h, l;
        split2(f0, f1, h, l);
        sW[k2 * P2_ + n] = make_uint2(h, l);
    }
    if (tid < HID_) { sB[tid] = bias[tid]; sG[tid] = gamma[tid]; sBt[tid] = beta[tid]; }
    __syncthreads();

    int warp = tid >> 5, lane = tid & 31;
    int g = lane >> 2, tig = lane & 3;

    for (int tile = blockIdx.x; tile < NTILES; tile += PGRID) {
        int blockbase = tile * 128;

        // ---- fused scatter (threads 0..127; latency hidden under GEMM) ----
        if (tid < 128) {
            int node = blockbase + tid;
            int b = node / N_;
            int n = node - b * N_;
            int bc = (b << 9) + cluster[node];
            int pos = atomicAdd(&g_cursor[bc], 1);
            g_binidx[(bc << 8) + pos] = n;
        }

        int wb = blockbase + warp * 16;        // warp's first node

        float acc[8][4];
#pragma unroll
        for (int t = 0; t < 8; t++)
#pragma unroll
            for (int c = 0; c < 4; c++) acc[t][c] = 0.f;

        const float2* xr0 = (const float2*)(x + (size_t)(wb + g) * INC_);
        const float2* xr1 = (const float2*)(x + (size_t)(wb + g + 8) * INC_);

#pragma unroll
        for (int kt = 0; kt < 8; kt++) {       // k-tiles of 16
            int k2base = kt * 8;
            float2 f00 = xr0[k2base + tig];
            float2 f10 = xr1[k2base + tig];
            float2 f01 = xr0[k2base + tig + 4];
            float2 f11 = xr1[k2base + tig + 4];

            unsigned ahi[4], alo[4];
            split2(f00.x, f00.y, ahi[0], alo[0]);
            split2(f10.x, f10.y, ahi[1], alo[1]);
            split2(f01.x, f01.y, ahi[2], alo[2]);
            split2(f11.x, f11.y, ahi[3], alo[3]);

            int ra = (k2base + tig) * P2_;
            int rb = (k2base + tig + 4) * P2_;
#pragma unroll
            for (int t = 0; t < 8; t++) {
                int ncol = t * 8 + g;
                uint2 w0 = sW[ra + ncol];      // (bh, bl) in one LDS64
                uint2 w1 = sW[rb + ncol];
                MMA_BF16(acc[t], ahi, w0.x, w1.x);   // hi * Hi
                MMA_BF16(acc[t], ahi, w0.y, w1.y);   // hi * Lo
                MMA_BF16(acc[t], alo, w0.x, w1.x);   // lo * Hi
            }
        }

        // ---- epilogue: bias, LN stats (quad-local), relu, store ----
        float s0 = 0.f, q0 = 0.f, s1 = 0.f, q1 = 0.f;
#pragma unroll
        for (int t = 0; t < 8; t++) {
            int n0 = t * 8 + 2 * tig;
            float b0v = sB[n0], b1v = sB[n0 + 1];
            acc[t][0] += b0v; acc[t][1] += b1v;    // row g
            acc[t][2] += b0v; acc[t][3] += b1v;    // row g+8
            s0 += acc[t][0] + acc[t][1];
            q0 = fmaf(acc[t][0], acc[t][0], q0);
            q0 = fmaf(acc[t][1], acc[t][1], q0);
            s1 += acc[t][2] + acc[t][3];
            q1 = fmaf(acc[t][2], acc[t][2], q1);
            q1 = fmaf(acc[t][3], acc[t][3], q1);
        }
#pragma unroll
        for (int w = 1; w <= 2; w <<= 1) {
            s0 += __shfl_xor_sync(0xffffffffu, s0, w);
            q0 += __shfl_xor_sync(0xffffffffu, q0, w);
            s1 += __shfl_xor_sync(0xffffffffu, s1, w);
            q1 += __shfl_xor_sync(0xffffffffu, q1, w);
        }
        float mu0 = s0 * (1.f / 64.f);
        float rs0 = rsqrtf(q0 * (1.f / 64.f) - mu0 * mu0 + 1e-5f);
        float mu1 = s1 * (1.f / 64.f);
        float rs1 = rsqrtf(q1 * (1.f / 64.f) - mu1 * mu1 + 1e-5f);

        float* o0 = out + (size_t)(wb + g) * 128;
        float* o1 = out + (size_t)(wb + g + 8) * 128;
#pragma unroll
        for (int t = 0; t < 8; t++) {
            int n0 = t * 8 + 2 * tig;
            float g0 = sG[n0], g1 = sG[n0 + 1], e0 = sBt[n0], e1 = sBt[n0 + 1];
            float2 v0, v1;
            v0.x = fmaxf(fmaf((acc[t][0] - mu0) * rs0, g0, e0), 0.f);
            v0.y = fmaxf(fmaf((acc[t][1] - mu0) * rs0, g1, e1), 0.f);
            v1.x = fmaxf(fmaf((acc[t][2] - mu1) * rs1, g0, e0), 0.f);
            v1.y = fmaxf(fmaf((acc[t][3] - mu1) * rs1, g1, e1), 0.f);
            *(float2*)(o0 + n0) = v0;
            *(float2*)(o1 + n0) = v1;
        }
    }
}

// ---------------------------------------------------------------------------
// WARP-PER-BIN segmax + broadcast: 8 independent warps per block, 1024 blocks.
// ~10x more bins in flight per SM than block-per-bin, and ZERO __syncthreads:
// staging is warp-local, the cross-row max is 2 shfl.xor steps (lane bits 3-4
// select the row-group). Lane = (rowlane = lane>>3, d8 = lane&7): 4 member
// rows in flight per warp, each row read/written as 2x128B coalesced.
// Lane 0 alone reads AND resets the cursor (race-free), shfl publishes it.
// ---------------------------------------------------------------------------
__global__ __launch_bounds__(256) void seg_kernel(float* __restrict__ out) {
    __shared__ int sidx[8][CAP_];

    int warp = threadIdx.x >> 5, lane = threadIdx.x & 31;
    int bc = blockIdx.x * 8 + warp;
    int b  = bc >> 9;
    int rowlane = lane >> 3;       // 4 entry lanes
    int d8      = lane & 7;        // float4 slots d8 and d8+8

    int cnt = 0;
    if (lane == 0) {
        cnt = g_cursor[bc];        // read-then-reset by ONE lane: race-free
        g_cursor[bc] = 0;          // ready for next graph replay
    }
    cnt = __shfl_sync(0xffffffffu, cnt, 0);

    for (int j = lane; j < cnt; j += 32)
        sidx[warp][j] = g_binidx[(bc << 8) + j];
    __syncwarp();

    size_t rowbase = (size_t)b * N_ * 128;

    float4 m0 = make_float4(-3.402823466e38f, -3.402823466e38f,
                            -3.402823466e38f, -3.402823466e38f);
    float4 m1 = m0;
    for (int i = rowlane; i < cnt; i += 4) {
        const float4* r = (const float4*)(out + rowbase + (size_t)sidx[warp][i] * 128);
        float4 v0 = r[d8], v1 = r[d8 + 8];
        m0.x = fmaxf(m0.x, v0.x); m0.y = fmaxf(m0.y, v0.y);
        m0.z = fmaxf(m0.z, v0.z); m0.w = fmaxf(m0.w, v0.w);
        m1.x = fmaxf(m1.x, v1.x); m1.y = fmaxf(m1.y, v1.y);
        m1.z = fmaxf(m1.z, v1.z); m1.w = fmaxf(m1.w, v1.w);
    }
    // combine the 4 row-groups: lanes differing in bits 3 (8) and 4 (16)
#pragma unroll
    for (int w = 8; w <= 16; w <<= 1) {
        m0.x = fmaxf(m0.x, __shfl_xor_sync(0xffffffffu, m0.x, w));
        m0.y = fmaxf(m0.y, __shfl_xor_sync(0xffffffffu, m0.y, w));
        m0.z = fmaxf(m0.z, __shfl_xor_sync(0xffffffffu, m0.z, w));
        m0.w = fmaxf(m0.w, __shfl_xor_sync(0xffffffffu, m0.w, w));
        m1.x = fmaxf(m1.x, __shfl_xor_sync(0xffffffffu, m1.x, w));
        m1.y = fmaxf(m1.y, __shfl_xor_sync(0xffffffffu, m1.y, w));
        m1.z = fmaxf(m1.z, __shfl_xor_sync(0xffffffffu, m1.z, w));
        m1.w = fmaxf(m1.w, __shfl_xor_sync(0xffffffffu, m1.w, w));
    }
    // broadcast the max row into every member's out[node][64:128]
    for (int i = rowlane; i < cnt; i += 4) {
        float4* w = (float4*)(out + rowbase + (size_t)sidx[warp][i] * 128 + 64);
        w[d8]     = m0;
        w[d8 + 8] = m1;
    }
}

// ---------------------------------------------------------------------------
extern "C" void kernel_launch(void* const* d_in, const int* in_sizes, int n_in,
                              void* d_out, int out_size) {
    const float* x       = (const float*)d_in[0];
    const int*   cluster = (const int*)  d_in[1];
    const float* W       = (const float*)d_in[2];
    const float* bias    = (const float*)d_in[3];
    const float* gamma   = (const float*)d_in[4];
    const float* beta    = (const float*)d_in[5];
    float* out = (float*)d_out;

    encode_kernel<<<PGRID, 256>>>(x, cluster, W, bias, gamma, beta, out);
    seg_kernel<<<BINS_ / 8, 256>>>(out);
}

// round 17
// speedup vs baseline: 1.2552x; 1.0078x over previous
#include <cuda_runtime.h>

#define B_     16
#define N_     50000
#define INC_   128
#define HID_   64
#define NC_    512
#define TOTAL_ (B_ * N_)     // 800000
#define BINS_  (B_ * NC_)    // 8192
#define CAP_   256           // fixed per-bin capacity (mean 97.7, sigma 9.9)
#define NTILES (TOTAL_ / 128)
#define P2_    68            // uint2 pitch: per half-warp, banks 8*tig+2g
                             // cover all 32 exactly once -> LDS64 conflict-free

// ---- scratch (no allocations allowed; __device__ globals, zero-init) ----
__device__ int g_cursor[BINS_];
__device__ int g_binidx[BINS_ * CAP_];       // bin bc at [bc<<8 ..]

// ---------------------------------------------------------------------------
// bf16 split helper: f = hi + lo (each bf16), packed as bf16x2 (lo half = f0).
// ---------------------------------------------------------------------------
__device__ __forceinline__ void split2(float f0, float f1,
                                       unsigned& hi, unsigned& lo) {
    unsigned h;
    asm("cvt.rn.bf16x2.f32 %0, %1, %2;" : "=r"(h) : "f"(f1), "f"(f0));
    float h0 = __uint_as_float(h << 16);
    float h1 = __uint_as_float(h & 0xffff0000u);
    float r0 = f0 - h0, r1 = f1 - h1;
    unsigned l;
    asm("cvt.rn.bf16x2.f32 %0, %1, %2;" : "=r"(l) : "f"(r1), "f"(r0));
    hi = h; lo = l;
}

#define MMA_BF16(c, a, b0v, b1v)                                              \
    asm volatile(                                                             \
        "mma.sync.aligned.m16n8k16.row.col.f32.bf16.bf16.f32 "                \
        "{%0,%1,%2,%3}, {%4,%5,%6,%7}, {%8,%9}, {%0,%1,%2,%3};"               \
        : "+f"((c)[0]), "+f"((c)[1]), "+f"((c)[2]), "+f"((c)[3])              \
        : "r"((a)[0]), "r"((a)[1]), "r"((a)[2]), "r"((a)[3]),                 \
          "r"(b0v), "r"(b1v))

// ---------------------------------------------------------------------------
// PERSISTENT encode on tensor cores: h = relu(LN(x @ W + b)), bf16x3 split.
// NEW: k-PERMUTED fragments. The k-order inside a k-tile is free as long as
// A and B agree, so each lane loads x with ONE LDG.128 (4 consecutive k) and
// calls its halves the fragment's lo/hi k-pairs; W staging applies the same
// permutation pi (index remap only). Halves x LDG ops AND x L1 wavefronts
// (8-line 32B/row pattern) at zero instruction/register cost.
// 296 blocks (2/SM) of 256 threads; W packed (hi,lo) uint2, pitch 68 (LDS64
// conflict-free). Fused cursor-scatter per tile. LN quad-local via shfl.
// ---------------------------------------------------------------------------
#define PGRID 296

__global__ __launch_bounds__(256, 2) void encode_kernel(
    const float* __restrict__ x, const int* __restrict__ cluster,
    const float* __restrict__ W,
    const float* __restrict__ bias, const float* __restrict__ gamma,
    const float* __restrict__ beta, float* __restrict__ out)
{
    __shared__ uint2 sW[64 * P2_];           // [logical k2][n] = (hi, lo)
    __shared__ float sB[HID_], sG[HID_], sBt[HID_];

    int tid = threadIdx.x;

    // ---- stage W once, pi-permuted: logical k2 -> global float pair ----
    // pi: within k-tile kt, logical lo pair q=tig <- globals {4tig, 4tig+1},
    //     logical hi pair q=tig+4 <- globals {4tig+2, 4tig+3}.
#pragma unroll
    for (int it = 0; it < 16; it++) {
        int idx = tid + it * 256;              // 4096 packed entries
        int k2 = idx >> 6, n = idx & 63;       // k2 = logical pair index
        int gb = ((k2 & ~7) << 1) + ((k2 & 3) << 2) + (((k2 >> 2) & 1) << 1);
        float f0 = W[gb * 64 + n];             // coalesced in n
        float f1 = W[(gb + 1) * 64 + n];
        unsigned h, l;
        split2(f0, f1, h, l);
        sW[k2 * P2_ + n] = make_uint2(h, l);
    }
    if (tid < HID_) { sB[tid] = bias[tid]; sG[tid] = gamma[tid]; sBt[tid] = beta[tid]; }
    __syncthreads();

    int warp = tid >> 5, lane = tid & 31;
    int g = lane >> 2, tig = lane & 3;

    for (int tile = blockIdx.x; tile < NTILES; tile += PGRID) {
        int blockbase = tile * 128;

        // ---- fused scatter (threads 0..127; latency hidden under GEMM) ----
        if (tid < 128) {
            int node = blockbase + tid;
            int b = node / N_;
            int n = node - b * N_;
            int bc = (b << 9) + cluster[node];
            int pos = atomicAdd(&g_cursor[bc], 1);
            g_binidx[(bc << 8) + pos] = n;
        }

        int wb = blockbase + warp * 16;        // warp's first node

        float acc[8][4];
#pragma unroll
        for (int t = 0; t < 8; t++)
#pragma unroll
            for (int c = 0; c < 4; c++) acc[t][c] = 0.f;

        const float4* xr0 = (const float4*)(x + (size_t)(wb + g) * INC_);
        const float4* xr1 = (const float4*)(x + (size_t)(wb + g + 8) * INC_);

#pragma unroll
        for (int kt = 0; kt < 8; kt++) {       // k-tiles of 16
            // one LDG.128 per row: float4 = 4 consecutive global k
            float4 v0 = xr0[kt * 4 + tig];     // row g
            float4 v1 = xr1[kt * 4 + tig];     // row g+8

            unsigned ahi[4], alo[4];
            split2(v0.x, v0.y, ahi[0], alo[0]);   // logical lo pair (q=tig)
            split2(v1.x, v1.y, ahi[1], alo[1]);
            split2(v0.z, v0.w, ahi[2], alo[2]);   // logical hi pair (q=tig+4)
            split2(v1.z, v1.w, ahi[3], alo[3]);

            int k2base = kt * 8;                  // logical pair index base
            int ra = (k2base + tig) * P2_;
            int rb = (k2base + tig + 4) * P2_;
#pragma unroll
            for (int t = 0; t < 8; t++) {
                int ncol = t * 8 + g;
                uint2 w0 = sW[ra + ncol];      // (bh, bl) in one LDS64
                uint2 w1 = sW[rb + ncol];
                MMA_BF16(acc[t], ahi, w0.x, w1.x);   // hi * Hi
                MMA_BF16(acc[t], ahi, w0.y, w1.y);   // hi * Lo
                MMA_BF16(acc[t], alo, w0.x, w1.x);   // lo * Hi
            }
        }

        // ---- epilogue: bias, LN stats (quad-local), relu, store ----
        float s0 = 0.f, q0 = 0.f, s1 = 0.f, q1 = 0.f;
#pragma unroll
        for (int t = 0; t < 8; t++) {
            int n0 = t * 8 + 2 * tig;
            float b0v = sB[n0], b1v = sB[n0 + 1];
            acc[t][0] += b0v; acc[t][1] += b1v;    // row g
            acc[t][2] += b0v; acc[t][3] += b1v;    // row g+8
            s0 += acc[t][0] + acc[t][1];
            q0 = fmaf(acc[t][0], acc[t][0], q0);
            q0 = fmaf(acc[t][1], acc[t][1], q0);
            s1 += acc[t][2] + acc[t][3];
            q1 = fmaf(acc[t][2], acc[t][2], q1);
            q1 = fmaf(acc[t][3], acc[t][3], q1);
        }
#pragma unroll
        for (int w = 1; w <= 2; w <<= 1) {
            s0 += __shfl_xor_sync(0xffffffffu, s0, w);
            q0 += __shfl_xor_sync(0xffffffffu, q0, w);
            s1 += __shfl_xor_sync(0xffffffffu, s1, w);
            q1 += __shfl_xor_sync(0xffffffffu, q1, w);
        }
        float mu0 = s0 * (1.f / 64.f);
        float rs0 = rsqrtf(q0 * (1.f / 64.f) - mu0 * mu0 + 1e-5f);
        float mu1 = s1 * (1.f / 64.f);
        float rs1 = rsqrtf(q1 * (1.f / 64.f) - mu1 * mu1 + 1e-5f);

        float* o0 = out + (size_t)(wb + g) * 128;
        float* o1 = out + (size_t)(wb + g + 8) * 128;
#pragma unroll
        for (int t = 0; t < 8; t++) {
            int n0 = t * 8 + 2 * tig;
            float g0 = sG[n0], g1 = sG[n0 + 1], e0 = sBt[n0], e1 = sBt[n0 + 1];
            float2 v0, v1;
            v0.x = fmaxf(fmaf((acc[t][0] - mu0) * rs0, g0, e0), 0.f);
            v0.y = fmaxf(fmaf((acc[t][1] - mu0) * rs0, g1, e1), 0.f);
            v1.x = fmaxf(fmaf((acc[t][2] - mu1) * rs1, g0, e0), 0.f);
            v1.y = fmaxf(fmaf((acc[t][3] - mu1) * rs1, g1, e1), 0.f);
            *(float2*)(o0 + n0) = v0;
            *(float2*)(o1 + n0) = v1;
        }
    }
}

// ---------------------------------------------------------------------------
// WARP-PER-BIN segmax + broadcast (unchanged; 84.6us, near scattered-row
// floor): 8 warps/block, 1024 blocks, zero __syncthreads. Lane = (rowlane,
// d8): 4 member rows in flight, 2x128B coalesced per row; cross-row max via
// 2 shfl.xor. Lane 0 reads AND resets the cursor (race-free).
// ---------------------------------------------------------------------------
__global__ __launch_bounds__(256) void seg_kernel(float* __restrict__ out) {
    __shared__ int sidx[8][CAP_];

    int warp = threadIdx.x >> 5, lane = threadIdx.x & 31;
    int bc = blockIdx.x * 8 + warp;
    int b  = bc >> 9;
    int rowlane = lane >> 3;       // 4 entry lanes
    int d8      = lane & 7;        // float4 slots d8 and d8+8

    int cnt = 0;
    if (lane == 0) {
        cnt = g_cursor[bc];        // read-then-reset by ONE lane: race-free
        g_cursor[bc] = 0;          // ready for next graph replay
    }
    cnt = __shfl_sync(0xffffffffu, cnt, 0);

    for (int j = lane; j < cnt; j += 32)
        sidx[warp][j] = g_binidx[(bc << 8) + j];
    __syncwarp();

    size_t rowbase = (size_t)b * N_ * 128;

    float4 m0 = make_float4(-3.402823466e38f, -3.402823466e38f,
                            -3.402823466e38f, -3.402823466e38f);
    float4 m1 = m0;
    for (int i = rowlane; i < cnt; i += 4) {
        const float4* r = (const float4*)(out + rowbase + (size_t)sidx[warp][i] * 128);
        float4 v0 = r[d8], v1 = r[d8 + 8];
        m0.x = fmaxf(m0.x, v0.x); m0.y = fmaxf(m0.y, v0.y);
        m0.z = fmaxf(m0.z, v0.z); m0.w = fmaxf(m0.w, v0.w);
        m1.x = fmaxf(m1.x, v1.x); m1.y = fmaxf(m1.y, v1.y);
        m1.z = fmaxf(m1.z, v1.z); m1.w = fmaxf(m1.w, v1.w);
    }
    // combine the 4 row-groups: lanes differing in bits 3 (8) and 4 (16)
#pragma unroll
    for (int w = 8; w <= 16; w <<= 1) {
        m0.x = fmaxf(m0.x, __shfl_xor_sync(0xffffffffu, m0.x, w));
        m0.y = fmaxf(m0.y, __shfl_xor_sync(0xffffffffu, m0.y, w));
        m0.z = fmaxf(m0.z, __shfl_xor_sync(0xffffffffu, m0.z, w));
        m0.w = fmaxf(m0.w, __shfl_xor_sync(0xffffffffu, m0.w, w));
        m1.x = fmaxf(m1.x, __shfl_xor_sync(0xffffffffu, m1.x, w));
        m1.y = fmaxf(m1.y, __shfl_xor_sync(0xffffffffu, m1.y, w));
        m1.z = fmaxf(m1.z, __shfl_xor_sync(0xffffffffu, m1.z, w));
        m1.w = fmaxf(m1.w, __shfl_xor_sync(0xffffffffu, m1.w, w));
    }
    // broadcast the max row into every member's out[node][64:128]
    for (int i = rowlane; i < cnt; i += 4) {
        float4* w = (float4*)(out + rowbase + (size_t)sidx[warp][i] * 128 + 64);
        w[d8]     = m0;
        w[d8 + 8] = m1;
    }
}

// ---------------------------------------------------------------------------
extern "C" void kernel_launch(void* const* d_in, const int* in_sizes, int n_in,
                              void* d_out, int out_size) {
    const float* x       = (const float*)d_in[0];
    const int*   cluster = (const int*)  d_in[1];
    const float* W       = (const float*)d_in[2];
    const float* bias    = (const float*)d_in[3];
    const float* gamma   = (const float*)d_in[4];
    const float* beta    = (const float*)d_in[5];
    float* out = (float*)d_out;

    encode_kernel<<<PGRID, 256>>>(x, cluster, W, bias, gamma, beta, out);
    seg_kernel<<<BINS_ / 8, 256>>>(out);
}